// round 12
// baseline (speedup 1.0000x reference)
#include <cuda_runtime.h>
#include <math.h>

#define Bn 32          // batch
#define Nt 32          // targets per batch
#define Sg 52          // grid size
#define SS (Sg*Sg)     // 2704
#define Cc 80          // classes
#define CELLS (3*SS)   // 8112 cells per batch
#define CPT 2          // cells per thread
#define GRPS (CELLS/CPT)       // 4056 groups per batch
#define BT  64         // block threads (2 warps)
#define NWARP (BT/32)  // 2 warps
#define NBX 64         // noobj blocks per batch (64*64*2 = 8192 >= 8112)
#define TOTB ((NBX+1)*Bn)          // 2080 blocks
#define NPART (Bn*NBX*NWARP + Bn)  // 4128 double partials (per-warp)
#define R3  1.7320508075688772f    // sqrt(3)
#define HR3 0.8660254037844386f    // sqrt(3)/2

// ANCHORS / stride (stride = 8); exact in binary
__constant__ float AW[9] = {14.5f, 19.5f, 46.625f, 3.75f, 7.75f, 7.375f, 1.25f, 2.0f, 4.125f};
__constant__ float AH[9] = {11.25f, 24.75f, 40.75f, 7.625f, 5.625f, 14.875f, 1.625f, 3.75f, 2.875f};

__device__ double       g_part[NPART];
__device__ int          g_nposi[Bn];
__device__ unsigned int g_ctr;   // zero-init; reset by the finalize block

__device__ __forceinline__ float tanh_ap(float x) {
    float y; asm("tanh.approx.f32 %0, %1;" : "=f"(y) : "f"(x)); return y;
}
// softplus(z) = log(1+e^z); equals reference BCE pieces for |z|<16 (inputs
// ~N(0,1)); BCE(z,t) = softplus(z) - t*z. Used identically in the noobj path
// and the corr undo path so the subtraction cancels exactly.
__device__ __forceinline__ float softplus(float z) {
    return __logf(1.f + __expf(z));
}

// Per-cell box setup + IoU>0.5 flags for NC cells. Targets pre-scaled by
// sqrt(3) so iw*ih = 3*inter and the test is FFMA(iw,ih,-tar) > ab.
//
// Exactness notes:
//  - One-clamp form: FFMA(max(iwr,0), ihr, -ta). If ihr<=0 the result is
//    <= -ta < 0 <= ab and cannot set the flag, so clamping ihr is unneeded.
//  - Y-screen: if ihr<=0 for ALL NC cells, every update is <= -ta < 0 and
//    the whole x-side can be skipped without affecting the flag.
//  - Same template for noobj (NC=2) and corr (NC=1) -> identical op sequence
//    -> bit-identical flag, so the corr undo cancels the noobj term exactly.
template <int NC>
__device__ __forceinline__ void cells_over(const float4* __restrict__ tb,
                                           const float*  __restrict__ tar,
                                           const float* zx, const float* zy,
                                           const float* zw, const float* zh,
                                           int i0, int j, int a,
                                           bool* over) {
    const float awa = AW[6 + a], aha = AH[6 + a];
    const float py3base = R3 * (0.5f + (float)j);
    float bx1[NC], by1[NC], bx2[NC], by2[NC], ab[NC], mm[NC];
    #pragma unroll
    for (int c = 0; c < NC; c++) {
        float thx = tanh_ap(0.5f * zx[c]);     // sigmoid = 0.5*tanh(z/2)+0.5
        float thy = tanh_ap(0.5f * zy[c]);
        float px3 = __fmaf_rn(HR3, thx, R3 * (0.5f + (float)(i0 + c)));
        float py3 = __fmaf_rn(HR3, thy, py3base);
        float pw  = __expf(zw[c]) * awa;
        float ph  = __expf(zh[c]) * aha;
        float hw3 = pw * HR3, hh3 = ph * HR3;
        bx1[c] = px3 - hw3; bx2[c] = px3 + hw3;
        by1[c] = py3 - hh3; by2[c] = py3 + hh3;
        ab[c]  = pw * ph;
        mm[c]  = -1e30f;
    }
    #pragma unroll 8
    for (int t = 0; t < Nt; t++) {
        const float4 q  = tb[t];
        const float  ta = tar[t];
        float ihr[NC];
        #pragma unroll
        for (int c = 0; c < NC; c++)
            ihr[c] = fminf(q.w, by2[c]) - fmaxf(q.y, by1[c]);
        float anyh = ihr[0];
        #pragma unroll
        for (int c = 1; c < NC; c++) anyh = fmaxf(anyh, ihr[c]);
        if (anyh > 0.f) {
            #pragma unroll
            for (int c = 0; c < NC; c++) {
                float iwr = fminf(q.z, bx2[c]) - fmaxf(q.x, bx1[c]);
                mm[c] = fmaxf(mm[c],
                              __fmaf_rn(fmaxf(iwr, 0.f), ihr[c], -ta));
            }
        }
    }
    #pragma unroll
    for (int c = 0; c < NC; c++) over[c] = (mm[c] > ab[c]);
}

__global__ void __launch_bounds__(BT) k_fused(const float* __restrict__ outp,
                                              const float* __restrict__ tgt,
                                              float* __restrict__ res) {
    __shared__ float4 tb[Nt];      // sqrt(3)-scaled target boxes
    __shared__ float  tar[Nt];     // unscaled target areas
    __shared__ double dred[BT];
    __shared__ int    sflat[Nt], scls[Nt], svalid[Nt];
    __shared__ int    lastflag;

    const int b    = blockIdx.y;
    const int bx   = blockIdx.x;
    const int tid  = threadIdx.x;
    const int lane = tid & 31;
    const int wid  = tid >> 5;

    if (tid < Nt) {
        const float* t = tgt + (b * Nt + tid) * 5;
        float gx = t[0] * 0.125f, gy = t[1] * 0.125f;
        float gw = t[2] * 0.125f, gh = t[3] * 0.125f;
        tb[tid]  = make_float4((gx - gw * 0.5f) * R3, (gy - gh * 0.5f) * R3,
                               (gx + gw * 0.5f) * R3, (gy + gh * 0.5f) * R3);
        tar[tid] = gw * gh;
    }
    if (tid == 0) lastflag = 0;
    __syncthreads();

    if (bx < NBX) {
        // ------------- noobj pass: 2 consecutive cells per thread -------------
        const int g = bx * BT + tid;           // cell group index
        float contrib = 0.f;
        if (g < GRPS) {
            const int m0   = g * CPT;
            const int a    = m0 / SS;          // same anchor (SS%2==0)
            const int rem0 = m0 - a * SS;
            const int j    = rem0 / Sg;        // same row (Sg%2==0)
            const int i0   = rem0 - j * Sg;

            const float* base = outp + (size_t)(b * 255 + a * 85) * SS + rem0;
            const float2 zx2 = *(const float2*)(base);
            const float2 zy2 = *(const float2*)(base + SS);
            const float2 zw2 = *(const float2*)(base + 2 * SS);
            const float2 zh2 = *(const float2*)(base + 3 * SS);
            const float2 zc2 = *(const float2*)(base + 4 * SS);
            const float zx[2] = {zx2.x, zx2.y};
            const float zy[2] = {zy2.x, zy2.y};
            const float zw[2] = {zw2.x, zw2.y};
            const float zh[2] = {zh2.x, zh2.y};
            const float zc[2] = {zc2.x, zc2.y};

            bool over[2];
            cells_over<2>(tb, tar, zx, zy, zw, zh, i0, j, a, over);
            if (!over[0]) contrib += softplus(zc[0]);
            if (!over[1]) contrib += softplus(zc[1]);
        }

        // per-warp partial straight to gmem (distinct addresses)
        #pragma unroll
        for (int s = 16; s > 0; s >>= 1)
            contrib += __shfl_down_sync(0xffffffffu, contrib, s);
        if (lane == 0)
            g_part[(b * NBX + bx) * NWARP + wid] = (double)contrib;
    } else {
        // ------------- correction pass: warp 0, one thread per target -------------
        if (tid < Nt) {
            const int n = tid;
            const float* t = tgt + (b * Nt + n) * 5;
            const float gx = t[0] * 0.125f, gy = t[1] * 0.125f;
            const float gw = t[2] * 0.125f, gh = t[3] * 0.125f;

            // anchor argmax over 9 (first max wins, matching jnp.argmax)
            float bestr = -1e30f; int best = 0;
            #pragma unroll
            for (int q = 0; q < 9; q++) {
                float inter = fminf(gw, AW[q]) * fminf(gh, AH[q]);
                float uni   = gw * gh + AW[q] * AH[q] - inter;
                float r = __fdividef(inter, uni);
                if (r > bestr) { bestr = r; best = q; }
            }
            const int valid = (best >= 6);
            const int k  = best - 6;
            const int gi = (int)floorf(gx);
            const int gj = (int)floorf(gy);
            const int flat = ((b * 3 + k) * Sg + gj) * Sg + gi;
            sflat[n] = flat; svalid[n] = valid; scls[n] = (int)t[4];
            __syncwarp();

            double corr = 0.0;
            bool winner = (valid != 0);
            for (int q = n + 1; q < Nt; q++)
                if (svalid[q] && sflat[q] == flat) winner = false;

            if (winner) {
                const float txv = gx - (float)gi;
                const float tyv = gy - (float)gj;
                const float twv = __logf(gw / AW[best]);
                const float thv = __logf(gh / AH[best]);
                const float scale = 2.f - (t[2] * (1.f / 416.f)) * (t[3] * (1.f / 416.f));

                const int rem = gj * Sg + gi;
                const float* base = outp + (size_t)(b * 255 + k * 85) * SS + rem;
                const float zx = base[0];
                const float zy = base[SS];
                const float zw = base[2 * SS];
                const float zh = base[3 * SS];
                const float zc = base[4 * SS];

                // identical per-cell op sequence -> same flag as noobj pass
                bool over[1];
                cells_over<1>(tb, tar, &zx, &zy, &zw, &zh, gi, gj, k, over);

                if (!over[0]) corr -= (double)softplus(zc);          // undo noobj
                corr += (double)(softplus(zc) - zc);                 // conf, t=1
                corr += (double)((softplus(zx) - txv * zx) * scale); // x BCE
                corr += (double)((softplus(zy) - tyv * zy) * scale); // y BCE
                const float dw = zw - twv, dh = zh - thv;
                corr += (double)(0.5f * dw * dw * scale);
                corr += (double)(0.5f * dh * dh * scale);

                // class one-hot = union over valid targets sharing this flat
                unsigned long long bits0 = 0ull, bits1 = 0ull;
                for (int q = 0; q < Nt; q++)
                    if (svalid[q] && sflat[q] == flat) {
                        int c = scls[q];
                        if (c < 64) bits0 |= 1ull << c;
                        else        bits1 |= 1ull << (c - 64);
                    }
                for (int c = 0; c < Cc; c++) {
                    float z = base[(5 + c) * SS];
                    bool on = (c < 64) ? ((bits0 >> c) & 1ull)
                                       : ((bits1 >> (c - 64)) & 1ull);
                    corr += (double)(softplus(z) - (on ? z : 0.f));
                }
            }

            unsigned bal = __ballot_sync(0xffffffffu, winner);
            #pragma unroll
            for (int s = 16; s > 0; s >>= 1)
                corr += __shfl_down_sync(0xffffffffu, corr, s);
            if (n == 0) {
                g_part[Bn * NBX * NWARP + b] = corr;
                g_nposi[b] = __popc(bal);
            }
        }
    }

    // ------------- last-block-done finalize -------------
    if (tid == 0) {
        __threadfence();
        if (atomicAdd(&g_ctr, 1u) == TOTB - 1) lastflag = 1;
    }
    __syncthreads();
    if (lastflag) {
        double s = 0.0;
        for (int i = tid; i < NPART; i += BT) s += g_part[i];
        dred[tid] = s;
        __syncthreads();
        #pragma unroll
        for (int q = BT/2; q > 0; q >>= 1) {
            if (tid < q) dred[tid] += dred[tid + q];
            __syncthreads();
        }
        int np = (tid < Bn) ? g_nposi[tid] : 0;
        if (tid < 32) {
            #pragma unroll
            for (int s2 = 16; s2 > 0; s2 >>= 1)
                np += __shfl_down_sync(0xffffffffu, np, s2);
        }
        if (tid == 0) {
            res[0] = (float)(dred[0] * (1.0 / (double)Bn));
            res[1] = fmaxf((float)np, 1.f);
            g_ctr = 0u;   // reset for next graph replay
        }
    }
}

extern "C" void kernel_launch(void* const* d_in, const int* in_sizes, int n_in,
                              void* d_out, int out_size) {
    const float* outp = (const float*)d_in[0];
    const float* tgt  = (const float*)d_in[1];
    float* res = (float*)d_out;
    k_fused<<<dim3(NBX + 1, Bn), BT>>>(outp, tgt, res);
}

// round 13
// speedup vs baseline: 1.2649x; 1.2649x over previous
#include <cuda_runtime.h>
#include <math.h>

#define Bn 32          // batch
#define Nt 32          // targets per batch
#define Sg 52          // grid size
#define SS (Sg*Sg)     // 2704
#define Cc 80          // classes
#define CELLS (3*SS)   // 8112 cells per batch
#define CPT 4          // cells per thread
#define GRPS (CELLS/CPT)       // 2028 groups per batch
#define BT  64         // block threads (2 warps)
#define NWARP (BT/32)  // 2 warps
#define NBX 32         // noobj blocks per batch (32*64*4 = 8192 >= 8112)
#define TOTB ((NBX+1)*Bn)          // 1056 blocks
#define NPART (Bn*NBX*NWARP + Bn)  // 2080 double partials (per-warp)
#define R3  1.7320508075688772f    // sqrt(3)
#define HR3 0.8660254037844386f    // sqrt(3)/2
#define THRC 0.5767729f            // 0.999/sqrt(3)  (conservative screen coeff)

// ANCHORS / stride (stride = 8); exact in binary
__constant__ float AW[9] = {14.5f, 19.5f, 46.625f, 3.75f, 7.75f, 7.375f, 1.25f, 2.0f, 4.125f};
__constant__ float AH[9] = {11.25f, 24.75f, 40.75f, 7.625f, 5.625f, 14.875f, 1.625f, 3.75f, 2.875f};

__device__ double       g_part[NPART];
__device__ int          g_nposi[Bn];
__device__ unsigned int g_ctr;   // zero-init; reset by the finalize block

__device__ __forceinline__ float tanh_ap(float x) {
    float y; asm("tanh.approx.f32 %0, %1;" : "=f"(y) : "f"(x)); return y;
}
// softplus(z) = log(1+e^z); equals reference BCE pieces for |z|<16 (inputs
// ~N(0,1)); BCE(z,t) = softplus(z) - t*z. Used identically in the noobj path
// and the corr undo path so the subtraction cancels exactly.
__device__ __forceinline__ float softplus(float z) {
    return __logf(1.f + __expf(z));
}

// Per-cell box setup + IoU>0.5 flags for NC cells. Target coords pre-scaled
// by sqrt(3) so iw*ih = 3*inter; the flag test is FFMA(iw,ih,-tar) > ab.
//
// Screen logic (per target t with threshold thr = gh*0.999/sqrt(3)):
//   iw_true <= gw  =>  3*inter <= 3*gw*ih_true, so 3*inter > tar needs
//   ih_true > gh/3, i.e. scaled ihr > gh_scaled/3 ~= thr. If ihr <= thr for
//   all NC cells, every update is <= ab and cannot change the flag -> skip
//   the whole x side INCLUDING its LDS.
// Same template for noobj (NC=4) and corr (NC=1) -> identical op sequence ->
// identical flags, so the corr undo cancels the noobj term exactly.
template <int NC>
__device__ __forceinline__ void cells_over(const float4* __restrict__ tby,
                                           const float2* __restrict__ tbx,
                                           const float* zx, const float* zy,
                                           const float* zw, const float* zh,
                                           int i0, int j, int a,
                                           bool* over) {
    const float awa = AW[6 + a], aha = AH[6 + a];
    const float py3base = R3 * (0.5f + (float)j);
    float bx1[NC], by1[NC], bx2[NC], by2[NC], ab[NC], mm[NC];
    #pragma unroll
    for (int c = 0; c < NC; c++) {
        float thx = tanh_ap(0.5f * zx[c]);     // sigmoid = 0.5*tanh(z/2)+0.5
        float thy = tanh_ap(0.5f * zy[c]);
        float px3 = __fmaf_rn(HR3, thx, R3 * (0.5f + (float)(i0 + c)));
        float py3 = __fmaf_rn(HR3, thy, py3base);
        float pw  = __expf(zw[c]) * awa;
        float ph  = __expf(zh[c]) * aha;
        float hw3 = pw * HR3, hh3 = ph * HR3;
        bx1[c] = px3 - hw3; bx2[c] = px3 + hw3;
        by1[c] = py3 - hh3; by2[c] = py3 + hh3;
        ab[c]  = pw * ph;
        mm[c]  = -1e30f;
    }
    #pragma unroll 8
    for (int t = 0; t < Nt; t++) {
        const float4 qy = tby[t];              // {y1, y2, thr, ta} one LDS.128
        float ihr[NC];
        #pragma unroll
        for (int c = 0; c < NC; c++)
            ihr[c] = fminf(qy.y, by2[c]) - fmaxf(qy.x, by1[c]);
        float anyh = ihr[0];
        #pragma unroll
        for (int c = 1; c < NC; c++) anyh = fmaxf(anyh, ihr[c]);
        if (anyh > qy.z) {                     // tight screen: ihr > gh/sqrt(3)
            const float2 qx = tbx[t];          // LDS.64 only when needed
            #pragma unroll
            for (int c = 0; c < NC; c++) {
                float iwr = fminf(qx.y, bx2[c]) - fmaxf(qx.x, bx1[c]);
                mm[c] = fmaxf(mm[c],
                              __fmaf_rn(fmaxf(iwr, 0.f), ihr[c], -qy.w));
            }
        }
    }
    #pragma unroll
    for (int c = 0; c < NC; c++) over[c] = (mm[c] > ab[c]);
}

__global__ void __launch_bounds__(BT) k_fused(const float* __restrict__ outp,
                                              const float* __restrict__ tgt,
                                              float* __restrict__ res) {
    __shared__ float4 tby[Nt];     // {y1s, y2s, thr, ta}
    __shared__ float2 tbx[Nt];     // {x1s, x2s}
    __shared__ double dred[BT];
    __shared__ int    sflat[Nt], scls[Nt], svalid[Nt];
    __shared__ int    lastflag;

    const int b    = blockIdx.y;
    const int bx   = blockIdx.x;
    const int tid  = threadIdx.x;
    const int lane = tid & 31;
    const int wid  = tid >> 5;

    if (tid < Nt) {
        const float* t = tgt + (b * Nt + tid) * 5;
        float gx = t[0] * 0.125f, gy = t[1] * 0.125f;
        float gw = t[2] * 0.125f, gh = t[3] * 0.125f;
        tby[tid] = make_float4((gy - gh * 0.5f) * R3, (gy + gh * 0.5f) * R3,
                               gh * THRC, gw * gh);
        tbx[tid] = make_float2((gx - gw * 0.5f) * R3, (gx + gw * 0.5f) * R3);
    }
    if (tid == 0) lastflag = 0;
    __syncthreads();

    if (bx < NBX) {
        // ------------- noobj pass: 4 consecutive cells per thread -------------
        const int g = bx * BT + tid;           // cell group index
        float contrib = 0.f;
        if (g < GRPS) {
            const int m0   = g * CPT;
            const int a    = m0 / SS;          // same anchor for all 4 (SS%4==0)
            const int rem0 = m0 - a * SS;
            const int j    = rem0 / Sg;        // same row for all 4 (Sg%4==0)
            const int i0   = rem0 - j * Sg;

            const float* base = outp + (size_t)(b * 255 + a * 85) * SS + rem0;
            const float4 zx4 = *(const float4*)(base);
            const float4 zy4 = *(const float4*)(base + SS);
            const float4 zw4 = *(const float4*)(base + 2 * SS);
            const float4 zh4 = *(const float4*)(base + 3 * SS);
            const float4 zc4 = *(const float4*)(base + 4 * SS);
            const float zx[4] = {zx4.x, zx4.y, zx4.z, zx4.w};
            const float zy[4] = {zy4.x, zy4.y, zy4.z, zy4.w};
            const float zw[4] = {zw4.x, zw4.y, zw4.z, zw4.w};
            const float zh[4] = {zh4.x, zh4.y, zh4.z, zh4.w};
            const float zc[4] = {zc4.x, zc4.y, zc4.z, zc4.w};

            bool over[4];
            cells_over<4>(tby, tbx, zx, zy, zw, zh, i0, j, a, over);
            #pragma unroll
            for (int c = 0; c < CPT; c++)
                if (!over[c]) contrib += softplus(zc[c]);
        }

        // per-warp partial straight to gmem (distinct addresses)
        #pragma unroll
        for (int s = 16; s > 0; s >>= 1)
            contrib += __shfl_down_sync(0xffffffffu, contrib, s);
        if (lane == 0)
            g_part[(b * NBX + bx) * NWARP + wid] = (double)contrib;
    } else {
        // ------------- correction pass: warp 0, one thread per target -------------
        if (tid < Nt) {
            const int n = tid;
            const float* t = tgt + (b * Nt + n) * 5;
            const float gx = t[0] * 0.125f, gy = t[1] * 0.125f;
            const float gw = t[2] * 0.125f, gh = t[3] * 0.125f;

            // anchor argmax over 9 (first max wins, matching jnp.argmax)
            float bestr = -1e30f; int best = 0;
            #pragma unroll
            for (int q = 0; q < 9; q++) {
                float inter = fminf(gw, AW[q]) * fminf(gh, AH[q]);
                float uni   = gw * gh + AW[q] * AH[q] - inter;
                float r = __fdividef(inter, uni);
                if (r > bestr) { bestr = r; best = q; }
            }
            const int valid = (best >= 6);
            const int k  = best - 6;
            const int gi = (int)floorf(gx);
            const int gj = (int)floorf(gy);
            const int flat = ((b * 3 + k) * Sg + gj) * Sg + gi;
            sflat[n] = flat; svalid[n] = valid; scls[n] = (int)t[4];
            __syncwarp();

            double corr = 0.0;
            bool winner = (valid != 0);
            for (int q = n + 1; q < Nt; q++)
                if (svalid[q] && sflat[q] == flat) winner = false;

            if (winner) {
                const float txv = gx - (float)gi;
                const float tyv = gy - (float)gj;
                const float twv = __logf(gw / AW[best]);
                const float thv = __logf(gh / AH[best]);
                const float scale = 2.f - (t[2] * (1.f / 416.f)) * (t[3] * (1.f / 416.f));

                const int rem = gj * Sg + gi;
                const float* base = outp + (size_t)(b * 255 + k * 85) * SS + rem;
                const float zx = base[0];
                const float zy = base[SS];
                const float zw = base[2 * SS];
                const float zh = base[3 * SS];
                const float zc = base[4 * SS];

                // identical per-cell op sequence -> same flag as noobj pass
                bool over[1];
                cells_over<1>(tby, tbx, &zx, &zy, &zw, &zh, gi, gj, k, over);

                if (!over[0]) corr -= (double)softplus(zc);          // undo noobj
                corr += (double)(softplus(zc) - zc);                 // conf, t=1
                corr += (double)((softplus(zx) - txv * zx) * scale); // x BCE
                corr += (double)((softplus(zy) - tyv * zy) * scale); // y BCE
                const float dw = zw - twv, dh = zh - thv;
                corr += (double)(0.5f * dw * dw * scale);
                corr += (double)(0.5f * dh * dh * scale);

                // class one-hot = union over valid targets sharing this flat
                unsigned long long bits0 = 0ull, bits1 = 0ull;
                for (int q = 0; q < Nt; q++)
                    if (svalid[q] && sflat[q] == flat) {
                        int c = scls[q];
                        if (c < 64) bits0 |= 1ull << c;
                        else        bits1 |= 1ull << (c - 64);
                    }
                for (int c = 0; c < Cc; c++) {
                    float z = base[(5 + c) * SS];
                    bool on = (c < 64) ? ((bits0 >> c) & 1ull)
                                       : ((bits1 >> (c - 64)) & 1ull);
                    corr += (double)(softplus(z) - (on ? z : 0.f));
                }
            }

            unsigned bal = __ballot_sync(0xffffffffu, winner);
            #pragma unroll
            for (int s = 16; s > 0; s >>= 1)
                corr += __shfl_down_sync(0xffffffffu, corr, s);
            if (n == 0) {
                g_part[Bn * NBX * NWARP + b] = corr;
                g_nposi[b] = __popc(bal);
            }
        }
    }

    // ------------- last-block-done finalize -------------
    if (tid == 0) {
        __threadfence();
        if (atomicAdd(&g_ctr, 1u) == TOTB - 1) lastflag = 1;
    }
    __syncthreads();
    if (lastflag) {
        double s = 0.0;
        for (int i = tid; i < NPART; i += BT) s += g_part[i];
        dred[tid] = s;
        __syncthreads();
        #pragma unroll
        for (int q = BT/2; q > 0; q >>= 1) {
            if (tid < q) dred[tid] += dred[tid + q];
            __syncthreads();
        }
        int np = (tid < Bn) ? g_nposi[tid] : 0;
        if (tid < 32) {
            #pragma unroll
            for (int s2 = 16; s2 > 0; s2 >>= 1)
                np += __shfl_down_sync(0xffffffffu, np, s2);
        }
        if (tid == 0) {
            res[0] = (float)(dred[0] * (1.0 / (double)Bn));
            res[1] = fmaxf((float)np, 1.f);
            g_ctr = 0u;   // reset for next graph replay
        }
    }
}

extern "C" void kernel_launch(void* const* d_in, const int* in_sizes, int n_in,
                              void* d_out, int out_size) {
    const float* outp = (const float*)d_in[0];
    const float* tgt  = (const float*)d_in[1];
    float* res = (float*)d_out;
    k_fused<<<dim3(NBX + 1, Bn), BT>>>(outp, tgt, res);
}

// round 15
// speedup vs baseline: 1.2667x; 1.0014x over previous
#include <cuda_runtime.h>
#include <math.h>

#define Bn 32          // batch
#define Nt 32          // targets per batch
#define Sg 52          // grid size
#define SS (Sg*Sg)     // 2704
#define Cc 80          // classes
#define CELLS (3*SS)   // 8112 cells per batch
#define CPT 4          // cells per thread
#define GRPS (CELLS/CPT)       // 2028 groups per batch
#define BT  64         // block threads (2 warps)
#define NWARP (BT/32)  // 2 warps
#define NBX 32         // noobj blocks per batch (32*64*4 = 8192 >= 8112)
#define TOTB ((NBX+1)*Bn)          // 1056 blocks
#define NPART (Bn*NBX*NWARP + Bn)  // 2080 double partials (per-warp)
#define R3  1.7320508075688772f    // sqrt(3)
#define HR3 0.8660254037844386f    // sqrt(3)/2
#define THRC 0.5767729f            // 0.999/sqrt(3)  (conservative screen coeff)

// ANCHORS / stride (stride = 8); exact in binary
__constant__ float AW[9] = {14.5f, 19.5f, 46.625f, 3.75f, 7.75f, 7.375f, 1.25f, 2.0f, 4.125f};
__constant__ float AH[9] = {11.25f, 24.75f, 40.75f, 7.625f, 5.625f, 14.875f, 1.625f, 3.75f, 2.875f};

__device__ double       g_part[NPART];
__device__ int          g_nposi[Bn];
__device__ unsigned int g_ctr;   // zero-init; reset by the finalize block

__device__ __forceinline__ float tanh_ap(float x) {
    float y; asm("tanh.approx.f32 %0, %1;" : "=f"(y) : "f"(x)); return y;
}
// softplus(z) = log(1+e^z); equals reference BCE pieces for |z|<16 (inputs
// ~N(0,1)); BCE(z,t) = softplus(z) - t*z. Used identically in the noobj path
// and the corr undo path so the subtraction cancels exactly.
__device__ __forceinline__ float softplus(float z) {
    return __logf(1.f + __expf(z));
}

// Per-cell box setup + IoU>0.5 flags for NC cells. Target coords pre-scaled
// by sqrt(3) so iw*ih = 3*inter; the flag test is FFMA(iw,ih,-tar) > ab.
//
// Screening (all conservative-EXACT — excluded targets provably cannot flip
// the flag):
//  1. thr-screen: iwr <= gw*sqrt(3), so contribution iwr*ihr - ta <=
//     gw*sqrt(3)*thr - ta = 0.999*gw*gh - gw*gh < 0 <= ab whenever
//     ihr <= thr = gh*0.999/sqrt(3). (0.999 absorbs rounding.)
//  2. Bound-screen: ihb = fmin(y2,bymax) - fmax(y1,bymin) >= ihr_c for every
//     cell c (fmin/fmax monotone, exact in FP). So ihb <= thr => all cells
//     screened => skip target entirely with a 2-op test.
//  3. One-clamp: FFMA(max(iwr,0), ihr, -ta) with ihr possibly negative gives
//     <= -ta < 0 <= ab -> no second clamp needed.
// Targets passing the screen run the identical mm-update op sequence in both
// noobj (NC=4) and corr (NC=1), so both flags equal the exact flag.
template <int NC>
__device__ __forceinline__ void cells_over(const float4* __restrict__ tby,
                                           const float2* __restrict__ tbx,
                                           const float* zx, const float* zy,
                                           const float* zw, const float* zh,
                                           int i0, int j, int a,
                                           bool* over) {
    const float awa = AW[6 + a], aha = AH[6 + a];
    const float py3base = R3 * (0.5f + (float)j);
    float bx1[NC], by1[NC], bx2[NC], by2[NC], ab[NC], mm[NC];
    #pragma unroll
    for (int c = 0; c < NC; c++) {
        float thx = tanh_ap(0.5f * zx[c]);     // sigmoid = 0.5*tanh(z/2)+0.5
        float thy = tanh_ap(0.5f * zy[c]);
        float px3 = __fmaf_rn(HR3, thx, R3 * (0.5f + (float)(i0 + c)));
        float py3 = __fmaf_rn(HR3, thy, py3base);
        float pw  = __expf(zw[c]) * awa;
        float ph  = __expf(zh[c]) * aha;
        float hw3 = pw * HR3, hh3 = ph * HR3;
        bx1[c] = px3 - hw3; bx2[c] = px3 + hw3;
        by1[c] = py3 - hh3; by2[c] = py3 + hh3;
        ab[c]  = pw * ph;
        mm[c]  = -1e30f;
    }
    // y bounding interval over this thread's NC cells
    float bymin = by1[0], bymax = by2[0];
    #pragma unroll
    for (int c = 1; c < NC; c++) {
        bymin = fminf(bymin, by1[c]);
        bymax = fmaxf(bymax, by2[c]);
    }
    #pragma unroll 8
    for (int t = 0; t < Nt; t++) {
        const float4 qy = tby[t];              // {y1, y2, thr, ta} one LDS.128
        const float ihb = fminf(qy.y, bymax) - fmaxf(qy.x, bymin);
        if (ihb > qy.z) {                      // 2-op conservative screen
            const float2 qx = tbx[t];          // LDS.64 only when needed
            #pragma unroll
            for (int c = 0; c < NC; c++) {
                float ihr = fminf(qy.y, by2[c]) - fmaxf(qy.x, by1[c]);
                float iwr = fminf(qx.y, bx2[c]) - fmaxf(qx.x, bx1[c]);
                mm[c] = fmaxf(mm[c],
                              __fmaf_rn(fmaxf(iwr, 0.f), ihr, -qy.w));
            }
        }
    }
    #pragma unroll
    for (int c = 0; c < NC; c++) over[c] = (mm[c] > ab[c]);
}

__global__ void __launch_bounds__(BT) k_fused(const float* __restrict__ outp,
                                              const float* __restrict__ tgt,
                                              float* __restrict__ res) {
    __shared__ float4 tby[Nt];     // {y1s, y2s, thr, ta}
    __shared__ float2 tbx[Nt];     // {x1s, x2s}
    __shared__ double dred[BT];
    __shared__ int    sflat[Nt], scls[Nt], svalid[Nt];
    __shared__ int    lastflag;

    const int b    = blockIdx.y;
    const int bx   = blockIdx.x;
    const int tid  = threadIdx.x;
    const int lane = tid & 31;
    const int wid  = tid >> 5;

    if (tid < Nt) {
        const float* t = tgt + (b * Nt + tid) * 5;
        float gx = t[0] * 0.125f, gy = t[1] * 0.125f;
        float gw = t[2] * 0.125f, gh = t[3] * 0.125f;
        tby[tid] = make_float4((gy - gh * 0.5f) * R3, (gy + gh * 0.5f) * R3,
                               gh * THRC, gw * gh);
        tbx[tid] = make_float2((gx - gw * 0.5f) * R3, (gx + gw * 0.5f) * R3);
    }
    if (tid == 0) lastflag = 0;
    __syncthreads();

    if (bx < NBX) {
        // ------------- noobj pass: 4 consecutive cells per thread -------------
        const int g = bx * BT + tid;           // cell group index
        float contrib = 0.f;
        if (g < GRPS) {
            const int m0   = g * CPT;
            const int a    = m0 / SS;          // same anchor for all 4 (SS%4==0)
            const int rem0 = m0 - a * SS;
            const int j    = rem0 / Sg;        // same row for all 4 (Sg%4==0)
            const int i0   = rem0 - j * Sg;

            const float* base = outp + (size_t)(b * 255 + a * 85) * SS + rem0;
            const float4 zx4 = *(const float4*)(base);
            const float4 zy4 = *(const float4*)(base + SS);
            const float4 zw4 = *(const float4*)(base + 2 * SS);
            const float4 zh4 = *(const float4*)(base + 3 * SS);
            const float4 zc4 = *(const float4*)(base + 4 * SS);
            const float zx[4] = {zx4.x, zx4.y, zx4.z, zx4.w};
            const float zy[4] = {zy4.x, zy4.y, zy4.z, zy4.w};
            const float zw[4] = {zw4.x, zw4.y, zw4.z, zw4.w};
            const float zh[4] = {zh4.x, zh4.y, zh4.z, zh4.w};
            const float zc[4] = {zc4.x, zc4.y, zc4.z, zc4.w};

            bool over[4];
            cells_over<4>(tby, tbx, zx, zy, zw, zh, i0, j, a, over);
            #pragma unroll
            for (int c = 0; c < CPT; c++)
                if (!over[c]) contrib += softplus(zc[c]);
        }

        // per-warp partial straight to gmem (distinct addresses)
        #pragma unroll
        for (int s = 16; s > 0; s >>= 1)
            contrib += __shfl_down_sync(0xffffffffu, contrib, s);
        if (lane == 0)
            g_part[(b * NBX + bx) * NWARP + wid] = (double)contrib;
    } else {
        // ------------- correction pass: warp 0, one thread per target -------------
        if (tid < Nt) {
            const int n = tid;
            const float* t = tgt + (b * Nt + n) * 5;
            const float gx = t[0] * 0.125f, gy = t[1] * 0.125f;
            const float gw = t[2] * 0.125f, gh = t[3] * 0.125f;

            // anchor argmax over 9 (first max wins, matching jnp.argmax)
            float bestr = -1e30f; int best = 0;
            #pragma unroll
            for (int q = 0; q < 9; q++) {
                float inter = fminf(gw, AW[q]) * fminf(gh, AH[q]);
                float uni   = gw * gh + AW[q] * AH[q] - inter;
                float r = __fdividef(inter, uni);
                if (r > bestr) { bestr = r; best = q; }
            }
            const int valid = (best >= 6);
            const int k  = best - 6;
            const int gi = (int)floorf(gx);
            const int gj = (int)floorf(gy);
            const int flat = ((b * 3 + k) * Sg + gj) * Sg + gi;
            sflat[n] = flat; svalid[n] = valid; scls[n] = (int)t[4];
            __syncwarp();

            double corr = 0.0;
            bool winner = (valid != 0);
            for (int q = n + 1; q < Nt; q++)
                if (svalid[q] && sflat[q] == flat) winner = false;

            if (winner) {
                const float txv = gx - (float)gi;
                const float tyv = gy - (float)gj;
                const float twv = __logf(gw / AW[best]);
                const float thv = __logf(gh / AH[best]);
                const float scale = 2.f - (t[2] * (1.f / 416.f)) * (t[3] * (1.f / 416.f));

                const int rem = gj * Sg + gi;
                const float* base = outp + (size_t)(b * 255 + k * 85) * SS + rem;
                const float zx = base[0];
                const float zy = base[SS];
                const float zw = base[2 * SS];
                const float zh = base[3 * SS];
                const float zc = base[4 * SS];

                // same conservative screens + identical mm-update sequence
                bool over[1];
                cells_over<1>(tby, tbx, &zx, &zy, &zw, &zh, gi, gj, k, over);

                if (!over[0]) corr -= (double)softplus(zc);          // undo noobj
                corr += (double)(softplus(zc) - zc);                 // conf, t=1
                corr += (double)((softplus(zx) - txv * zx) * scale); // x BCE
                corr += (double)((softplus(zy) - tyv * zy) * scale); // y BCE
                const float dw = zw - twv, dh = zh - thv;
                corr += (double)(0.5f * dw * dw * scale);
                corr += (double)(0.5f * dh * dh * scale);

                // class one-hot = union over valid targets sharing this flat
                unsigned long long bits0 = 0ull, bits1 = 0ull;
                for (int q = 0; q < Nt; q++)
                    if (svalid[q] && sflat[q] == flat) {
                        int c = scls[q];
                        if (c < 64) bits0 |= 1ull << c;
                        else        bits1 |= 1ull << (c - 64);
                    }
                for (int c = 0; c < Cc; c++) {
                    float z = base[(5 + c) * SS];
                    bool on = (c < 64) ? ((bits0 >> c) & 1ull)
                                       : ((bits1 >> (c - 64)) & 1ull);
                    corr += (double)(softplus(z) - (on ? z : 0.f));
                }
            }

            unsigned bal = __ballot_sync(0xffffffffu, winner);
            #pragma unroll
            for (int s = 16; s > 0; s >>= 1)
                corr += __shfl_down_sync(0xffffffffu, corr, s);
            if (n == 0) {
                g_part[Bn * NBX * NWARP + b] = corr;
                g_nposi[b] = __popc(bal);
            }
        }
    }

    // ------------- last-block-done finalize -------------
    if (tid == 0) {
        __threadfence();
        if (atomicAdd(&g_ctr, 1u) == TOTB - 1) lastflag = 1;
    }
    __syncthreads();
    if (lastflag) {
        double s = 0.0;
        for (int i = tid; i < NPART; i += BT) s += g_part[i];
        dred[tid] = s;
        __syncthreads();
        #pragma unroll
        for (int q = BT/2; q > 0; q >>= 1) {
            if (tid < q) dred[tid] += dred[tid + q];
            __syncthreads();
        }
        int np = (tid < Bn) ? g_nposi[tid] : 0;
        if (tid < 32) {
            #pragma unroll
            for (int s2 = 16; s2 > 0; s2 >>= 1)
                np += __shfl_down_sync(0xffffffffu, np, s2);
        }
        if (tid == 0) {
            res[0] = (float)(dred[0] * (1.0 / (double)Bn));
            res[1] = fmaxf((float)np, 1.f);
            g_ctr = 0u;   // reset for next graph replay
        }
    }
}

extern "C" void kernel_launch(void* const* d_in, const int* in_sizes, int n_in,
                              void* d_out, int out_size) {
    const float* outp = (const float*)d_in[0];
    const float* tgt  = (const float*)d_in[1];
    float* res = (float*)d_out;
    k_fused<<<dim3(NBX + 1, Bn), BT>>>(outp, tgt, res);
}